// round 1
// baseline (speedup 1.0000x reference)
#include <cuda_runtime.h>
#include <math.h>

// Problem dims (fixed by the reference)
#define BDIM 8
#define CDIM 1024
#define QDIM 128
#define EDIM 512
#define HDIM 1024
#define FDIM 2048   // 4*E

// ---------------- scratch (static device globals; no allocation) ----------------
__device__ float g_qm[BDIM * QDIM * EDIM];     // question * w_multiple
__device__ float g_qw[BDIM * QDIM];            // question @ w_question
__device__ float g_cw[BDIM * CDIM];            // context @ w_context
__device__ float g_rowmax[BDIM * CDIM];        // max_q sim
__device__ float g_q2c[BDIM * EDIM];
__device__ float g_att[BDIM * CDIM * FDIM];    // attended (B*C, 2048)
__device__ float g_h[BDIM * CDIM * HDIM];      // hidden (B*C, 1024)

// ---------------- prep kernels ----------------
__global__ __launch_bounds__(128) void prep_q_kernel(const float* __restrict__ question,
                                                     const float* __restrict__ wq,
                                                     const float* __restrict__ wm) {
    int row = blockIdx.x;   // b*Q + q
    int tid = threadIdx.x;
    float partial = 0.f;
#pragma unroll
    for (int i = 0; i < 4; i++) {
        int e = tid + 128 * i;
        float v = question[row * EDIM + e];
        g_qm[row * EDIM + e] = v * wm[e];
        partial += v * wq[e];
    }
#pragma unroll
    for (int o = 16; o; o >>= 1) partial += __shfl_xor_sync(0xffffffffu, partial, o);
    __shared__ float red[4];
    if ((tid & 31) == 0) red[tid >> 5] = partial;
    __syncthreads();
    if (tid == 0) g_qw[row] = red[0] + red[1] + red[2] + red[3];
}

__global__ __launch_bounds__(128) void prep_c_kernel(const float* __restrict__ context,
                                                     const float* __restrict__ wc) {
    int row = blockIdx.x;   // b*C + c
    int tid = threadIdx.x;
    float partial = 0.f;
#pragma unroll
    for (int i = 0; i < 4; i++) {
        int e = tid + 128 * i;
        partial += context[row * EDIM + e] * wc[e];
    }
#pragma unroll
    for (int o = 16; o; o >>= 1) partial += __shfl_xor_sync(0xffffffffu, partial, o);
    __shared__ float red[4];
    if ((tid & 31) == 0) red[tid >> 5] = partial;
    __syncthreads();
    if (tid == 0) g_cw[row] = red[0] + red[1] + red[2] + red[3];
}

// ---------------- fused attention kernel ----------------
// Block = (b, 64 context rows). 256 threads (16x16 microtile grid).
// Phase 1: sim[64][128] = ctx_tile @ qm^T  (+ qw + cw)
// Phase 2: row softmax over q, record raw rowmax
// Phase 3: c2q[64][512] = P @ question; write attended parts 0..2
__global__ __launch_bounds__(256) void attn_kernel(const float* __restrict__ context,
                                                   const float* __restrict__ question) {
    // shared layout (union via raw buffer):
    //  phase1: A1[64][36] (ctx, [m][k]) + B1[128][36] (qm, [n][k])  -> 6912 floats
    //  phase2/3: S[64][132] (sim/P)      + Qs[64][36] (question^T)  -> 10752 floats
    __shared__ __align__(16) float smbuf[64 * 132 + 64 * 36];
    float (*S)[132]  = (float(*)[132]) smbuf;
    float (*Qs)[36]  = (float(*)[36]) (smbuf + 64 * 132);
    float (*A1)[36]  = (float(*)[36]) smbuf;
    float (*B1)[36]  = (float(*)[36]) (smbuf + 64 * 36);

    int b = blockIdx.y;
    int c0 = blockIdx.x * 64;
    int tid = threadIdx.x;
    int tm = tid >> 4;      // 0..15 (m groups of 4 interleaved rows)
    int tn = tid & 15;      // 0..15 (n groups)

    float acc[4][8];
#pragma unroll
    for (int i = 0; i < 4; i++)
#pragma unroll
        for (int j = 0; j < 8; j++) acc[i][j] = 0.f;

    // ---- Phase 1: sim = ctx @ qm^T over E in 32-wide chunks ----
    for (int e0 = 0; e0 < EDIM; e0 += 32) {
        // ctx tile 64x32 -> A1[r][k]
#pragma unroll
        for (int i = 0; i < 2; i++) {
            int lin = tid + 256 * i;            // 0..511  (64 rows * 8 float4)
            int r = lin >> 3, c4 = (lin & 7) * 4;
            float4 v = *(const float4*)&context[(b * CDIM + c0 + r) * EDIM + e0 + c4];
            *(float4*)&A1[r][c4] = v;
        }
        // qm tile 128x32 -> B1[r][k]
#pragma unroll
        for (int i = 0; i < 4; i++) {
            int lin = tid + 256 * i;            // 0..1023 (128 rows * 8 float4)
            int r = lin >> 3, c4 = (lin & 7) * 4;
            float4 v = *(const float4*)&g_qm[(b * QDIM + r) * EDIM + e0 + c4];
            *(float4*)&B1[r][c4] = v;
        }
        __syncthreads();
#pragma unroll
        for (int k = 0; k < 32; k += 4) {
            float4 av[4], bv[8];
#pragma unroll
            for (int i = 0; i < 4; i++) av[i] = *(const float4*)&A1[tm + 16 * i][k];
#pragma unroll
            for (int j = 0; j < 8; j++) bv[j] = *(const float4*)&B1[tn + 16 * j][k];
#pragma unroll
            for (int i = 0; i < 4; i++)
#pragma unroll
                for (int j = 0; j < 8; j++) {
                    acc[i][j] += av[i].x * bv[j].x;
                    acc[i][j] += av[i].y * bv[j].y;
                    acc[i][j] += av[i].z * bv[j].z;
                    acc[i][j] += av[i].w * bv[j].w;
                }
        }
        __syncthreads();
    }

    // ---- Phase 2: write S (+broadcast terms), softmax over q ----
    float qwv[8], cwv[4];
#pragma unroll
    for (int j = 0; j < 8; j++) qwv[j] = g_qw[b * QDIM + tn + 16 * j];
#pragma unroll
    for (int i = 0; i < 4; i++) cwv[i] = g_cw[b * CDIM + c0 + tm + 16 * i];
#pragma unroll
    for (int i = 0; i < 4; i++)
#pragma unroll
        for (int j = 0; j < 8; j++)
            S[tm + 16 * i][tn + 16 * j] = acc[i][j] + qwv[j] + cwv[i];
    __syncthreads();

    {
        int warp = tid >> 5, lane = tid & 31;
        for (int r = warp; r < 64; r += 8) {
            float v0 = S[r][lane], v1 = S[r][lane + 32], v2 = S[r][lane + 64], v3 = S[r][lane + 96];
            float mx = fmaxf(fmaxf(v0, v1), fmaxf(v2, v3));
#pragma unroll
            for (int o = 16; o; o >>= 1) mx = fmaxf(mx, __shfl_xor_sync(0xffffffffu, mx, o));
            float p0 = __expf(v0 - mx), p1 = __expf(v1 - mx), p2 = __expf(v2 - mx), p3 = __expf(v3 - mx);
            float s = p0 + p1 + p2 + p3;
#pragma unroll
            for (int o = 16; o; o >>= 1) s += __shfl_xor_sync(0xffffffffu, s, o);
            float inv = 1.f / s;
            S[r][lane] = p0 * inv; S[r][lane + 32] = p1 * inv;
            S[r][lane + 64] = p2 * inv; S[r][lane + 96] = p3 * inv;
            if (lane == 0) g_rowmax[b * CDIM + c0 + r] = mx;
        }
    }
    __syncthreads();

    // ---- Phase 3: c2q = P @ question, write attended parts 0..2 ----
    for (int eo = 0; eo < EDIM; eo += 64) {
        float acc2[4][4];
#pragma unroll
        for (int i = 0; i < 4; i++)
#pragma unroll
            for (int j = 0; j < 4; j++) acc2[i][j] = 0.f;

        for (int kq = 0; kq < QDIM; kq += 32) {
            // question chunk 32(q) x 64(e), stored transposed Qs[e_local][q_local]
#pragma unroll
            for (int i = 0; i < 2; i++) {
                int lin = tid + 256 * i;          // 0..511 (32 rows * 16 float4)
                int r = lin >> 4, c4 = (lin & 15) * 4;
                float4 v = *(const float4*)&question[(b * QDIM + kq + r) * EDIM + eo + c4];
                Qs[c4 + 0][r] = v.x; Qs[c4 + 1][r] = v.y;
                Qs[c4 + 2][r] = v.z; Qs[c4 + 3][r] = v.w;
            }
            __syncthreads();
#pragma unroll
            for (int kk = 0; kk < 32; kk += 4) {
                float4 av[4], bv[4];
#pragma unroll
                for (int i = 0; i < 4; i++) av[i] = *(const float4*)&S[tm + 16 * i][kq + kk];
#pragma unroll
                for (int j = 0; j < 4; j++) bv[j] = *(const float4*)&Qs[tn + 16 * j][kk];
#pragma unroll
                for (int i = 0; i < 4; i++)
#pragma unroll
                    for (int j = 0; j < 4; j++) {
                        acc2[i][j] += av[i].x * bv[j].x;
                        acc2[i][j] += av[i].y * bv[j].y;
                        acc2[i][j] += av[i].z * bv[j].z;
                        acc2[i][j] += av[i].w * bv[j].w;
                    }
            }
            __syncthreads();
        }
        // epilogue: attended[:, 0:E]=ctx, [E:2E]=c2q, [2E:3E]=ctx*c2q
#pragma unroll
        for (int i = 0; i < 4; i++) {
            int row = b * CDIM + c0 + tm + 16 * i;
#pragma unroll
            for (int j = 0; j < 4; j++) {
                int e = eo + tn + 16 * j;
                float cv = context[row * EDIM + e];
                float cq = acc2[i][j];
                g_att[row * FDIM + e] = cv;
                g_att[row * FDIM + EDIM + e] = cq;
                g_att[row * FDIM + 2 * EDIM + e] = cv * cq;
            }
        }
    }
}

// ---------------- q2c: softmax over C of rowmax, weighted context sum ----------------
__global__ __launch_bounds__(512) void q2c_kernel(const float* __restrict__ context) {
    int b = blockIdx.x, tid = threadIdx.x;
    int lane = tid & 31, warp = tid >> 5;
    __shared__ float alpha[CDIM];
    __shared__ float red[16];

    float r0 = g_rowmax[b * CDIM + tid];
    float r1 = g_rowmax[b * CDIM + 512 + tid];
    float mx = fmaxf(r0, r1);
#pragma unroll
    for (int o = 16; o; o >>= 1) mx = fmaxf(mx, __shfl_xor_sync(0xffffffffu, mx, o));
    if (lane == 0) red[warp] = mx;
    __syncthreads();
    if (tid < 32) {
        float m = (tid < 16) ? red[tid] : -3.402823e38f;
#pragma unroll
        for (int o = 8; o; o >>= 1) m = fmaxf(m, __shfl_xor_sync(0xffffffffu, m, o));
        if (tid == 0) red[0] = m;
    }
    __syncthreads();
    mx = red[0];
    __syncthreads();

    float e0v = __expf(r0 - mx), e1v = __expf(r1 - mx);
    float s = e0v + e1v;
#pragma unroll
    for (int o = 16; o; o >>= 1) s += __shfl_xor_sync(0xffffffffu, s, o);
    if (lane == 0) red[warp] = s;
    __syncthreads();
    if (tid < 32) {
        float t = (tid < 16) ? red[tid] : 0.f;
#pragma unroll
        for (int o = 8; o; o >>= 1) t += __shfl_xor_sync(0xffffffffu, t, o);
        if (tid == 0) red[0] = t;
    }
    __syncthreads();
    float inv = 1.f / red[0];
    alpha[tid] = e0v * inv;
    alpha[tid + 512] = e1v * inv;
    __syncthreads();

    float acc = 0.f;
    const float* cb = context + b * CDIM * EDIM + tid;  // tid = e
#pragma unroll 8
    for (int c = 0; c < CDIM; c++) acc += alpha[c] * cb[c * EDIM];
    g_q2c[b * EDIM + tid] = acc;
}

// ---------------- attended part 3 = ctx * q2c ----------------
__global__ __launch_bounds__(256) void fill_kernel(const float* __restrict__ context) {
    int idx = blockIdx.x * 256 + threadIdx.x;   // over B*C*E
    int row = idx >> 9;         // / EDIM
    int e = idx & (EDIM - 1);
    int b = row >> 10;          // / CDIM
    g_att[row * FDIM + 3 * EDIM + e] = context[idx] * g_q2c[b * EDIM + e];
}

// ---------------- double-buffered SGEMM: 128x128x16, 256 threads, 8x8 microtile ----------------
// MODE 0: h   = (att @ W1 + b1) * mask          (M=8192, N=1024, K=2048)
// MODE 1: out = relu((h @ W2 + b2) * mask)      (M=8192, N=2048, K=1024)
template <int MODE>
__global__ __launch_bounds__(256) void sgemm_kernel(const float* __restrict__ Wm,
                                                    const float* __restrict__ bias,
                                                    const float* __restrict__ mask,
                                                    float* __restrict__ outp) {
    constexpr int N = (MODE == 0) ? HDIM : FDIM;
    constexpr int K = (MODE == 0) ? FDIM : HDIM;
    const float* __restrict__ A = (MODE == 0) ? g_att : g_h;
    float* C = (MODE == 0) ? g_h : outp;

    __shared__ __align__(16) float As[2][16][132];   // [k][m], transposed store
    __shared__ __align__(16) float Bs[2][16][132];   // [k][n]

    int tid = threadIdx.x;
    int bm = blockIdx.y * 128, bn = blockIdx.x * 128;
    int tx = tid & 15, ty = tid >> 4;
    int a_row = tid >> 2, a_kc = (tid & 3) * 4;      // each thread: rows a_row & a_row+64
    int b_row = tid >> 5, b_nc = (tid & 31) * 4;     // each thread: k-rows b_row & b_row+8

    float acc[8][8] = {};

    // initial tile (kt=0)
    {
        float4 pA0 = *(const float4*)&A[(bm + a_row) * K + a_kc];
        float4 pA1 = *(const float4*)&A[(bm + a_row + 64) * K + a_kc];
        float4 pB0 = *(const float4*)&Wm[b_row * N + bn + b_nc];
        float4 pB1 = *(const float4*)&Wm[(b_row + 8) * N + bn + b_nc];
#pragma unroll
        for (int jj = 0; jj < 4; jj++) {
            As[0][a_kc + jj][a_row]      = ((float*)&pA0)[jj];
            As[0][a_kc + jj][a_row + 64] = ((float*)&pA1)[jj];
        }
        *(float4*)&Bs[0][b_row][b_nc] = pB0;
        *(float4*)&Bs[0][b_row + 8][b_nc] = pB1;
    }
    __syncthreads();

    int buf = 0;
    const int nk = K / 16;
    for (int kt = 0; kt < nk; ++kt) {
        float4 pA0, pA1, pB0, pB1;
        if (kt + 1 < nk) {
            int k0 = (kt + 1) * 16;
            pA0 = *(const float4*)&A[(bm + a_row) * K + k0 + a_kc];
            pA1 = *(const float4*)&A[(bm + a_row + 64) * K + k0 + a_kc];
            pB0 = *(const float4*)&Wm[(k0 + b_row) * N + bn + b_nc];
            pB1 = *(const float4*)&Wm[(k0 + b_row + 8) * N + bn + b_nc];
        }
#pragma unroll
        for (int k = 0; k < 16; k++) {
            float4 a0 = *(const float4*)&As[buf][k][ty * 4];
            float4 a1 = *(const float4*)&As[buf][k][ty * 4 + 64];
            float4 b0 = *(const float4*)&Bs[buf][k][tx * 4];
            float4 b1 = *(const float4*)&Bs[buf][k][tx * 4 + 64];
            float av[8] = {a0.x, a0.y, a0.z, a0.w, a1.x, a1.y, a1.z, a1.w};
            float bv[8] = {b0.x, b0.y, b0.z, b0.w, b1.x, b1.y, b1.z, b1.w};
#pragma unroll
            for (int i = 0; i < 8; i++)
#pragma unroll
                for (int j = 0; j < 8; j++) acc[i][j] += av[i] * bv[j];
        }
        if (kt + 1 < nk) {
            int nb = buf ^ 1;
#pragma unroll
            for (int jj = 0; jj < 4; jj++) {
                As[nb][a_kc + jj][a_row]      = ((float*)&pA0)[jj];
                As[nb][a_kc + jj][a_row + 64] = ((float*)&pA1)[jj];
            }
            *(float4*)&Bs[nb][b_row][b_nc] = pB0;
            *(float4*)&Bs[nb][b_row + 8][b_nc] = pB1;
            __syncthreads();
            buf = nb;
        }
    }

    // epilogue: bias, mask, optional relu
#pragma unroll
    for (int gi = 0; gi < 2; ++gi)
#pragma unroll
        for (int ii = 0; ii < 4; ++ii) {
            int r = bm + gi * 64 + ty * 4 + ii;
            float mk = mask[r];
#pragma unroll
            for (int gj = 0; gj < 2; ++gj) {
                int cbase = bn + gj * 64 + tx * 4;
                const float* a = &acc[gi * 4 + ii][gj * 4];
                float4 v;
                v.x = (a[0] + bias[cbase + 0]) * mk;
                v.y = (a[1] + bias[cbase + 1]) * mk;
                v.z = (a[2] + bias[cbase + 2]) * mk;
                v.w = (a[3] + bias[cbase + 3]) * mk;
                if (MODE == 1) {
                    v.x = fmaxf(v.x, 0.f); v.y = fmaxf(v.y, 0.f);
                    v.z = fmaxf(v.z, 0.f); v.w = fmaxf(v.w, 0.f);
                }
                *(float4*)&C[r * N + cbase] = v;
            }
        }
}

// ---------------- launch ----------------
extern "C" void kernel_launch(void* const* d_in, const int* in_sizes, int n_in,
                              void* d_out, int out_size) {
    const float* context    = (const float*)d_in[0];
    const float* question   = (const float*)d_in[1];
    const float* mask       = (const float*)d_in[2];
    const float* w_question = (const float*)d_in[3];
    const float* w_context  = (const float*)d_in[4];
    const float* w_multiple = (const float*)d_in[5];
    const float* W1 = (const float*)d_in[6];
    const float* b1 = (const float*)d_in[7];
    const float* W2 = (const float*)d_in[8];
    const float* b2 = (const float*)d_in[9];
    float* out = (float*)d_out;

    prep_q_kernel<<<BDIM * QDIM, 128>>>(question, w_question, w_multiple);
    prep_c_kernel<<<BDIM * CDIM, 128>>>(context, w_context);
    attn_kernel<<<dim3(CDIM / 64, BDIM), 256>>>(context, question);
    q2c_kernel<<<BDIM, 512>>>(context);
    fill_kernel<<<(BDIM * CDIM * EDIM) / 256, 256>>>(context);
    sgemm_kernel<0><<<dim3(HDIM / 128, (BDIM * CDIM) / 128), 256>>>(W1, b1, mask, nullptr);
    sgemm_kernel<1><<<dim3(FDIM / 128, (BDIM * CDIM) / 128), 256>>>(W2, b2, mask, out);
}

// round 7
// speedup vs baseline: 2.2049x; 2.2049x over previous
#include <cuda_runtime.h>
#include <cuda_bf16.h>
#include <cstdint>
#include <math.h>

// Problem dims (fixed by the reference)
#define BDIM 8
#define CDIM 1024
#define QDIM 128
#define EDIM 512
#define HDIM 1024
#define FDIM 2048   // 4*E

// ---------------- scratch (static device globals; no allocation) ----------------
// NOTE: these symbols are ONLY referenced from device code. Passing them as
// kernel arguments from host code yields the HOST shadow address (silently
// dereferenceable on GB300 via ATS) — that was the R6 rel_err=1.0 bug.
__device__ __align__(128) float g_qm[BDIM * QDIM * EDIM];     // question * w_multiple
__device__ float g_qw[BDIM * QDIM];            // question @ w_question
__device__ float g_cw[BDIM * CDIM];            // context @ w_context
__device__ float g_rowmax[BDIM * CDIM];        // max_q sim
__device__ float g_alpha[BDIM * CDIM];         // softmax over C of rowmax
__device__ float g_q2c[BDIM * EDIM];

// bf16 hi/lo split operands for tensor-core GEMMs
__device__ __align__(128) __nv_bfloat16 g_att_h[BDIM * CDIM * FDIM];
__device__ __align__(128) __nv_bfloat16 g_att_l[BDIM * CDIM * FDIM];
__device__ __align__(128) __nv_bfloat16 g_h_h[BDIM * CDIM * HDIM];
__device__ __align__(128) __nv_bfloat16 g_h_l[BDIM * CDIM * HDIM];
__device__ __align__(128) __nv_bfloat16 g_w1t_h[HDIM * FDIM];  // [N=1024][K=2048]
__device__ __align__(128) __nv_bfloat16 g_w1t_l[HDIM * FDIM];
__device__ __align__(128) __nv_bfloat16 g_w2t_h[FDIM * HDIM];  // [N=2048][K=1024]
__device__ __align__(128) __nv_bfloat16 g_w2t_l[FDIM * HDIM];

// ---------------- small PTX helpers (base sm_103 ISA ONLY: no tcgen05) ----------------
static __device__ __forceinline__ uint32_t smem_u32(const void* p) {
    uint32_t a;
    asm("{ .reg .u64 t; cvta.to.shared.u64 t, %1; cvt.u32.u64 %0, t; }" : "=r"(a) : "l"(p));
    return a;
}
static __device__ __forceinline__ void cp16(uint32_t dst, const void* src) {
    asm volatile("cp.async.cg.shared.global [%0], [%1], 16;" :: "r"(dst), "l"(src));
}
#define CP_COMMIT() asm volatile("cp.async.commit_group;" ::: "memory")
#define CP_WAIT(n)  asm volatile("cp.async.wait_group %0;" :: "n"(n) : "memory")

#define SW128(o) ((o) ^ (((o) >> 3) & 0x70))

#define LDSM4(r0, r1, r2, r3, addr) \
    asm volatile("ldmatrix.sync.aligned.m8n8.x4.shared.b16 {%0,%1,%2,%3}, [%4];" \
        : "=r"(r0), "=r"(r1), "=r"(r2), "=r"(r3) : "r"(addr))

#define MMA16816(d, a, b0, b1) \
    asm volatile("mma.sync.aligned.m16n8k16.row.col.f32.bf16.bf16.f32 " \
        "{%0,%1,%2,%3}, {%4,%5,%6,%7}, {%8,%9}, {%0,%1,%2,%3};" \
        : "+f"((d)[0]), "+f"((d)[1]), "+f"((d)[2]), "+f"((d)[3]) \
        : "r"((a)[0]), "r"((a)[1]), "r"((a)[2]), "r"((a)[3]), "r"(b0), "r"(b1))

static __device__ __forceinline__ void split_bf16(float v, __nv_bfloat16& hi, __nv_bfloat16& lo) {
    hi = __float2bfloat16(v);
    lo = __float2bfloat16(v - __bfloat162float(hi));
}

// ---------------- prep kernels ----------------
__global__ __launch_bounds__(128) void prep_q_kernel(const float* __restrict__ question,
                                                     const float* __restrict__ wq,
                                                     const float* __restrict__ wm) {
    int row = blockIdx.x;
    int tid = threadIdx.x;
    float partial = 0.f;
#pragma unroll
    for (int i = 0; i < 4; i++) {
        int e = tid + 128 * i;
        float v = question[row * EDIM + e];
        g_qm[row * EDIM + e] = v * wm[e];
        partial += v * wq[e];
    }
#pragma unroll
    for (int o = 16; o; o >>= 1) partial += __shfl_xor_sync(0xffffffffu, partial, o);
    __shared__ float red[4];
    if ((tid & 31) == 0) red[tid >> 5] = partial;
    __syncthreads();
    if (tid == 0) g_qw[row] = red[0] + red[1] + red[2] + red[3];
}

__global__ __launch_bounds__(128) void prep_c_kernel(const float* __restrict__ context,
                                                     const float* __restrict__ wc) {
    int row = blockIdx.x;
    int tid = threadIdx.x;
    float partial = 0.f;
#pragma unroll
    for (int i = 0; i < 4; i++) {
        int e = tid + 128 * i;
        partial += context[row * EDIM + e] * wc[e];
    }
#pragma unroll
    for (int o = 16; o; o >>= 1) partial += __shfl_xor_sync(0xffffffffu, partial, o);
    __shared__ float red[4];
    if ((tid & 31) == 0) red[tid >> 5] = partial;
    __syncthreads();
    if (tid == 0) g_cw[row] = red[0] + red[1] + red[2] + red[3];
}

// ---------------- W transpose + bf16 split: W[K][N] -> T[N][K] hi/lo ----------------
// WHICH 0: W1 (K=FDIM rows, N=HDIM cols) -> g_w1t;  WHICH 1: W2 (K=HDIM, N=FDIM) -> g_w2t
template <int WHICH>
__global__ __launch_bounds__(256) void wtrans_kernel(const float* __restrict__ W) {
    constexpr int R     = (WHICH == 0) ? FDIM : HDIM;   // K length of output rows
    constexpr int Ccols = (WHICH == 0) ? HDIM : FDIM;   // N
    __nv_bfloat16* __restrict__ Th = (WHICH == 0) ? g_w1t_h : g_w2t_h;  // device-side binding
    __nv_bfloat16* __restrict__ Tl = (WHICH == 0) ? g_w1t_l : g_w2t_l;

    __shared__ float t[32][33];
    int n0 = blockIdx.x * 32, k0 = blockIdx.y * 32;
    int tx = threadIdx.x & 31, ty = threadIdx.x >> 5;  // 32x8
#pragma unroll
    for (int i = 0; i < 4; i++)
        t[ty + 8 * i][tx] = W[(size_t)(k0 + ty + 8 * i) * Ccols + n0 + tx];
    __syncthreads();
#pragma unroll
    for (int i = 0; i < 4; i++) {
        int orow = n0 + ty + 8 * i;
        float v = t[tx][ty + 8 * i];
        __nv_bfloat16 hi, lo;
        split_bf16(v, hi, lo);
        Th[(size_t)orow * R + k0 + tx] = hi;
        Tl[(size_t)orow * R + k0 + tx] = lo;
    }
}

// ---------------- fused attention kernel ----------------
__global__ __launch_bounds__(256) void attn_kernel(const float* __restrict__ context,
                                                   const float* __restrict__ question) {
    __shared__ __align__(16) float smbuf[64 * 132 + 64 * 36];
    float (*S)[132]  = (float(*)[132]) smbuf;
    float (*Qs)[36]  = (float(*)[36]) (smbuf + 64 * 132);
    float (*A1)[36]  = (float(*)[36]) smbuf;
    float (*B1)[36]  = (float(*)[36]) (smbuf + 64 * 36);

    int b = blockIdx.y;
    int c0 = blockIdx.x * 64;
    int tid = threadIdx.x;
    int tm = tid >> 4;
    int tn = tid & 15;

    float acc[4][8];
#pragma unroll
    for (int i = 0; i < 4; i++)
#pragma unroll
        for (int j = 0; j < 8; j++) acc[i][j] = 0.f;

    for (int e0 = 0; e0 < EDIM; e0 += 32) {
#pragma unroll
        for (int i = 0; i < 2; i++) {
            int lin = tid + 256 * i;
            int r = lin >> 3, c4 = (lin & 7) * 4;
            float4 v = *(const float4*)&context[(b * CDIM + c0 + r) * EDIM + e0 + c4];
            *(float4*)&A1[r][c4] = v;
        }
#pragma unroll
        for (int i = 0; i < 4; i++) {
            int lin = tid + 256 * i;
            int r = lin >> 3, c4 = (lin & 7) * 4;
            float4 v = *(const float4*)&g_qm[(b * QDIM + r) * EDIM + e0 + c4];
            *(float4*)&B1[r][c4] = v;
        }
        __syncthreads();
#pragma unroll
        for (int k = 0; k < 32; k += 4) {
            float4 av[4], bv[8];
#pragma unroll
            for (int i = 0; i < 4; i++) av[i] = *(const float4*)&A1[tm + 16 * i][k];
#pragma unroll
            for (int j = 0; j < 8; j++) bv[j] = *(const float4*)&B1[tn + 16 * j][k];
#pragma unroll
            for (int i = 0; i < 4; i++)
#pragma unroll
                for (int j = 0; j < 8; j++) {
                    acc[i][j] += av[i].x * bv[j].x;
                    acc[i][j] += av[i].y * bv[j].y;
                    acc[i][j] += av[i].z * bv[j].z;
                    acc[i][j] += av[i].w * bv[j].w;
                }
        }
        __syncthreads();
    }

    float qwv[8], cwv[4];
#pragma unroll
    for (int j = 0; j < 8; j++) qwv[j] = g_qw[b * QDIM + tn + 16 * j];
#pragma unroll
    for (int i = 0; i < 4; i++) cwv[i] = g_cw[b * CDIM + c0 + tm + 16 * i];
#pragma unroll
    for (int i = 0; i < 4; i++)
#pragma unroll
        for (int j = 0; j < 8; j++)
            S[tm + 16 * i][tn + 16 * j] = acc[i][j] + qwv[j] + cwv[i];
    __syncthreads();

    {
        int warp = tid >> 5, lane = tid & 31;
        for (int r = warp; r < 64; r += 8) {
            float v0 = S[r][lane], v1 = S[r][lane + 32], v2 = S[r][lane + 64], v3 = S[r][lane + 96];
            float mx = fmaxf(fmaxf(v0, v1), fmaxf(v2, v3));
#pragma unroll
            for (int o = 16; o; o >>= 1) mx = fmaxf(mx, __shfl_xor_sync(0xffffffffu, mx, o));
            float p0 = __expf(v0 - mx), p1 = __expf(v1 - mx), p2 = __expf(v2 - mx), p3 = __expf(v3 - mx);
            float s = p0 + p1 + p2 + p3;
#pragma unroll
            for (int o = 16; o; o >>= 1) s += __shfl_xor_sync(0xffffffffu, s, o);
            float inv = 1.f / s;
            S[r][lane] = p0 * inv; S[r][lane + 32] = p1 * inv;
            S[r][lane + 64] = p2 * inv; S[r][lane + 96] = p3 * inv;
            if (lane == 0) g_rowmax[b * CDIM + c0 + r] = mx;
        }
    }
    __syncthreads();

    for (int eo = 0; eo < EDIM; eo += 64) {
        float acc2[4][4];
#pragma unroll
        for (int i = 0; i < 4; i++)
#pragma unroll
            for (int j = 0; j < 4; j++) acc2[i][j] = 0.f;

        for (int kq = 0; kq < QDIM; kq += 32) {
#pragma unroll
            for (int i = 0; i < 2; i++) {
                int lin = tid + 256 * i;
                int r = lin >> 4, c4 = (lin & 15) * 4;
                float4 v = *(const float4*)&question[(b * QDIM + kq + r) * EDIM + eo + c4];
                Qs[c4 + 0][r] = v.x; Qs[c4 + 1][r] = v.y;
                Qs[c4 + 2][r] = v.z; Qs[c4 + 3][r] = v.w;
            }
            __syncthreads();
#pragma unroll
            for (int kk = 0; kk < 32; kk += 4) {
                float4 av[4], bv[4];
#pragma unroll
                for (int i = 0; i < 4; i++) av[i] = *(const float4*)&S[tm + 16 * i][kq + kk];
#pragma unroll
                for (int j = 0; j < 4; j++) bv[j] = *(const float4*)&Qs[tn + 16 * j][kk];
#pragma unroll
                for (int i = 0; i < 4; i++)
#pragma unroll
                    for (int j = 0; j < 4; j++) {
                        acc2[i][j] += av[i].x * bv[j].x;
                        acc2[i][j] += av[i].y * bv[j].y;
                        acc2[i][j] += av[i].z * bv[j].z;
                        acc2[i][j] += av[i].w * bv[j].w;
                    }
            }
            __syncthreads();
        }
#pragma unroll
        for (int i = 0; i < 4; i++) {
            int row = b * CDIM + c0 + tm + 16 * i;
#pragma unroll
            for (int j = 0; j < 4; j++) {
                int e = eo + tn + 16 * j;
                float cv = context[row * EDIM + e];
                float cq = acc2[i][j];
                __nv_bfloat16 hi, lo;
                split_bf16(cv, hi, lo);
                g_att_h[(size_t)row * FDIM + e] = hi;
                g_att_l[(size_t)row * FDIM + e] = lo;
                split_bf16(cq, hi, lo);
                g_att_h[(size_t)row * FDIM + EDIM + e] = hi;
                g_att_l[(size_t)row * FDIM + EDIM + e] = lo;
                split_bf16(cv * cq, hi, lo);
                g_att_h[(size_t)row * FDIM + 2 * EDIM + e] = hi;
                g_att_l[(size_t)row * FDIM + 2 * EDIM + e] = lo;
            }
        }
    }
}

// ---------------- alpha: softmax over C of rowmax (also zeroes g_q2c) ----------------
__global__ __launch_bounds__(512) void alpha_kernel() {
    int b = blockIdx.x, tid = threadIdx.x;
    int lane = tid & 31, warp = tid >> 5;
    __shared__ float red[16];

    float r0 = g_rowmax[b * CDIM + tid];
    float r1 = g_rowmax[b * CDIM + 512 + tid];
    float mx = fmaxf(r0, r1);
#pragma unroll
    for (int o = 16; o; o >>= 1) mx = fmaxf(mx, __shfl_xor_sync(0xffffffffu, mx, o));
    if (lane == 0) red[warp] = mx;
    __syncthreads();
    if (tid < 32) {
        float m = (tid < 16) ? red[tid] : -3.402823e38f;
#pragma unroll
        for (int o = 8; o; o >>= 1) m = fmaxf(m, __shfl_xor_sync(0xffffffffu, m, o));
        if (tid == 0) red[0] = m;
    }
    __syncthreads();
    mx = red[0];
    __syncthreads();

    float e0v = __expf(r0 - mx), e1v = __expf(r1 - mx);
    float s = e0v + e1v;
#pragma unroll
    for (int o = 16; o; o >>= 1) s += __shfl_xor_sync(0xffffffffu, s, o);
    if (lane == 0) red[warp] = s;
    __syncthreads();
    if (tid < 32) {
        float t = (tid < 16) ? red[tid] : 0.f;
#pragma unroll
        for (int o = 8; o; o >>= 1) t += __shfl_xor_sync(0xffffffffu, t, o);
        if (tid == 0) red[0] = t;
    }
    __syncthreads();
    float inv = 1.f / red[0];
    g_alpha[b * CDIM + tid] = e0v * inv;
    g_alpha[b * CDIM + 512 + tid] = e1v * inv;
    g_q2c[b * EDIM + tid] = 0.f;   // EDIM == 512 == blockDim
}

// ---------------- q2c accumulate: grid (B, 8), 128 c-rows per block ----------------
__global__ __launch_bounds__(256) void q2c_acc_kernel(const float* __restrict__ context) {
    int b = blockIdx.x, cj = blockIdx.y, t = threadIdx.x;
    __shared__ float al[128];
    if (t < 128) al[t] = g_alpha[b * CDIM + cj * 128 + t];
    __syncthreads();
    float a0 = 0.f, a1 = 0.f;
    const float* base = context + (size_t)(b * CDIM + cj * 128) * EDIM;
#pragma unroll 4
    for (int c = 0; c < 128; c++) {
        float av = al[c];
        a0 += av * base[c * EDIM + t];
        a1 += av * base[c * EDIM + t + 256];
    }
    atomicAdd(&g_q2c[b * EDIM + t], a0);
    atomicAdd(&g_q2c[b * EDIM + t + 256], a1);
}

// ---------------- attended part 3 = ctx * q2c (bf16 hi/lo) ----------------
__global__ __launch_bounds__(256) void fill_kernel(const float* __restrict__ context) {
    int idx = blockIdx.x * 256 + threadIdx.x;
    int row = idx >> 9;
    int e = idx & (EDIM - 1);
    int b = row >> 10;
    float v = context[idx] * g_q2c[b * EDIM + e];
    __nv_bfloat16 hi, lo;
    split_bf16(v, hi, lo);
    g_att_h[(size_t)row * FDIM + 3 * EDIM + e] = hi;
    g_att_l[(size_t)row * FDIM + 3 * EDIM + e] = lo;
}

// ---------------- mma.sync bf16 split GEMM (base ISA, no tcgen05) ----------------
// D[M,N] = Ah*Bh^T + Ah*Bl^T + Al*Bh^T, fp32 accumulate in registers.
// Tile 128x128x64; 256 threads; warp grid 2(M)x4(N); warp tile 64x32; m16n8k16.
// All operand arrays bound INSIDE device code (host-passed symbols were the bug).
// MODE 0: h = (att @ W1 + b1)*mask -> bf16 hi/lo      (N=1024, K=2048)
// MODE 1: out = relu((h @ W2 + b2)*mask) -> fp32       (N=2048, K=1024)
#define GSM_TOTAL (65536 + 1024)

template <int MODE>
__global__ __launch_bounds__(256) void mma_gemm_kernel(
    const float* __restrict__ bias, const float* __restrict__ mask,
    float* __restrict__ outp)
{
    constexpr int N   = (MODE == 0) ? HDIM : FDIM;
    constexpr int K   = (MODE == 0) ? FDIM : HDIM;
    constexpr int NKC = K / 64;        // 64-wide K chunks per segment
    constexpr int NKT = 3 * NKC;       // 3 split segments

    // device-side operand binding (real device addresses)
    const __nv_bfloat16* __restrict__ Ah = (MODE == 0) ? g_att_h : g_h_h;
    const __nv_bfloat16* __restrict__ Al = (MODE == 0) ? g_att_l : g_h_l;
    const __nv_bfloat16* __restrict__ Bh = (MODE == 0) ? g_w1t_h : g_w2t_h;
    const __nv_bfloat16* __restrict__ Bl = (MODE == 0) ? g_w1t_l : g_w2t_l;

    extern __shared__ char dsm[];
    uint32_t sb = (smem_u32(dsm) + 1023u) & ~1023u;

    int tid = threadIdx.x;
    int wid = tid >> 5, lane = tid & 31;
    int wm = wid & 1;                  // M half (0/1): rows 64*wm
    int wn = wid >> 1;                 // N quarter (0..3): cols 32*wn
    int bm = blockIdx.y * 128, bn = blockIdx.x * 128;

    // ---- stage loader: A 128x64 + B 128x64 bf16, SW128 ----
    auto load_tiles = [&](int it, int buf) {
        int s  = it / NKC;
        int k0 = (it - s * NKC) * 64;
        const __nv_bfloat16* Aseg = (s == 2) ? Al : Ah;
        const __nv_bfloat16* Bseg = (s == 1) ? Bl : Bh;
        uint32_t abase = sb + buf * 32768;
        uint32_t bbase = abase + 16384;
#pragma unroll
        for (int i = 0; i < 4; i++) {
            int lin = tid + 256 * i;          // 1024 16B chunks
            int r = lin >> 3, c = lin & 7;
            cp16(abase + SW128(r * 128 + c * 16), Aseg + (size_t)(bm + r) * K + k0 + c * 8);
        }
#pragma unroll
        for (int i = 0; i < 4; i++) {
            int lin = tid + 256 * i;
            int r = lin >> 3, c = lin & 7;
            cp16(bbase + SW128(r * 128 + c * 16), Bseg + (size_t)(bn + r) * K + k0 + c * 8);
        }
        CP_COMMIT();
    };

    float acc[4][4][4];
#pragma unroll
    for (int i = 0; i < 4; i++)
#pragma unroll
        for (int j = 0; j < 4; j++)
#pragma unroll
            for (int q = 0; q < 4; q++) acc[i][j][q] = 0.f;

    // Per-lane ldmatrix address components
    int arow_l = (lane & 15);
    int akb    = ((lane >> 4) & 1) * 16;
    int brow_l = (lane & 7) + ((lane >> 4) << 3);
    int bkb    = ((lane >> 3) & 1) * 16;

    load_tiles(0, 0);

    for (int it = 0; it < NKT; ++it) {
        int buf = it & 1;
        if (it + 1 < NKT) {
            load_tiles(it + 1, buf ^ 1);
            CP_WAIT(1);
        } else {
            CP_WAIT(0);
        }
        __syncthreads();

        uint32_t abase = sb + buf * 32768;
        uint32_t bbase = abase + 16384;

#pragma unroll
        for (int ks = 0; ks < 4; ks++) {
            uint32_t a[4][4];
#pragma unroll
            for (int i = 0; i < 4; i++) {
                int row = 64 * wm + 16 * i + arow_l;
                uint32_t addr = abase + row * 128 + ((ks * 32 + akb) ^ ((row & 7) << 4));
                LDSM4(a[i][0], a[i][1], a[i][2], a[i][3], addr);
            }
            uint32_t bfr[4][2];
#pragma unroll
            for (int p = 0; p < 2; p++) {
                int row = 32 * wn + 16 * p + brow_l;
                uint32_t addr = bbase + row * 128 + ((ks * 32 + bkb) ^ ((row & 7) << 4));
                LDSM4(bfr[2 * p][0], bfr[2 * p][1], bfr[2 * p + 1][0], bfr[2 * p + 1][1], addr);
            }
#pragma unroll
            for (int i = 0; i < 4; i++)
#pragma unroll
                for (int j = 0; j < 4; j++)
                    MMA16816(acc[i][j], a[i], bfr[j][0], bfr[j][1]);
        }
        __syncthreads();   // protect buf before it is refilled next iteration
    }

    // ---- epilogue: straight from registers ----
    int r_base = bm + 64 * wm + (lane >> 2);
    int c_base = bn + 32 * wn + 2 * (lane & 3);
#pragma unroll
    for (int i = 0; i < 4; i++) {
        int r0 = r_base + 16 * i;
        int r1 = r0 + 8;
        float mk0 = mask[r0], mk1 = mask[r1];
#pragma unroll
        for (int j = 0; j < 4; j++) {
            int col = c_base + 8 * j;
            float bz0 = bias[col], bz1 = bias[col + 1];
            float v00 = (acc[i][j][0] + bz0) * mk0;
            float v01 = (acc[i][j][1] + bz1) * mk0;
            float v10 = (acc[i][j][2] + bz0) * mk1;
            float v11 = (acc[i][j][3] + bz1) * mk1;
            if (MODE == 0) {
                __nv_bfloat16 h0, l0, h1, l1;
                split_bf16(v00, h0, l0); split_bf16(v01, h1, l1);
                uint32_t hw = (uint32_t)__bfloat16_as_ushort(h0) |
                              ((uint32_t)__bfloat16_as_ushort(h1) << 16);
                uint32_t lw = (uint32_t)__bfloat16_as_ushort(l0) |
                              ((uint32_t)__bfloat16_as_ushort(l1) << 16);
                *(uint32_t*)&g_h_h[(size_t)r0 * N + col] = hw;
                *(uint32_t*)&g_h_l[(size_t)r0 * N + col] = lw;
                split_bf16(v10, h0, l0); split_bf16(v11, h1, l1);
                hw = (uint32_t)__bfloat16_as_ushort(h0) |
                     ((uint32_t)__bfloat16_as_ushort(h1) << 16);
                lw = (uint32_t)__bfloat16_as_ushort(l0) |
                     ((uint32_t)__bfloat16_as_ushort(l1) << 16);
                *(uint32_t*)&g_h_h[(size_t)r1 * N + col] = hw;
                *(uint32_t*)&g_h_l[(size_t)r1 * N + col] = lw;
            } else {
                float2 o0 = make_float2(fmaxf(v00, 0.f), fmaxf(v01, 0.f));
                float2 o1 = make_float2(fmaxf(v10, 0.f), fmaxf(v11, 0.f));
                *(float2*)&outp[(size_t)r0 * N + col] = o0;
                *(float2*)&outp[(size_t)r1 * N + col] = o1;
            }
        }
    }
}

// ---------------- launch ----------------
extern "C" void kernel_launch(void* const* d_in, const int* in_sizes, int n_in,
                              void* d_out, int out_size) {
    const float* context    = (const float*)d_in[0];
    const float* question   = (const float*)d_in[1];
    const float* mask       = (const float*)d_in[2];
    const float* w_question = (const float*)d_in[3];
    const float* w_context  = (const float*)d_in[4];
    const float* w_multiple = (const float*)d_in[5];
    const float* W1 = (const float*)d_in[6];
    const float* b1 = (const float*)d_in[7];
    const float* W2 = (const float*)d_in[8];
    const float* b2 = (const float*)d_in[9];
    float* out = (float*)d_out;

    cudaFuncSetAttribute(mma_gemm_kernel<0>, cudaFuncAttributeMaxDynamicSharedMemorySize, GSM_TOTAL);
    cudaFuncSetAttribute(mma_gemm_kernel<1>, cudaFuncAttributeMaxDynamicSharedMemorySize, GSM_TOTAL);

    prep_q_kernel<<<BDIM * QDIM, 128>>>(question, w_question, w_multiple);
    prep_c_kernel<<<BDIM * CDIM, 128>>>(context, w_context);
    wtrans_kernel<0><<<dim3(HDIM / 32, FDIM / 32), 256>>>(W1);
    wtrans_kernel<1><<<dim3(FDIM / 32, HDIM / 32), 256>>>(W2);
    attn_kernel<<<dim3(CDIM / 64, BDIM), 256>>>(context, question);
    alpha_kernel<<<BDIM, 512>>>();
    q2c_acc_kernel<<<dim3(BDIM, 8), 256>>>(context);
    fill_kernel<<<(BDIM * CDIM * EDIM) / 256, 256>>>(context);
    mma_gemm_kernel<0><<<dim3(HDIM / 128, (BDIM * CDIM) / 128), 256, GSM_TOTAL>>>(b1, mask, nullptr);
    mma_gemm_kernel<1><<<dim3(FDIM / 128, (BDIM * CDIM) / 128), 256, GSM_TOTAL>>>(b2, mask, out);
}